// round 2
// baseline (speedup 1.0000x reference)
#include <cuda_runtime.h>
#include <cstdint>

// MultiBackScatter: three chained scatter-adds with UNIQUE (permutation) indices.
// Composition: out[idx0[idx1[idx2[i]]]] = x[i]; all other rows zero.
//
// Strategy: build inverse map inv[r] = source row (or -1), then ONE streaming
// pass over the 410MB output (write roofline) that emits zeros or the x row.
// This removes the serialized scatter kernel from the critical path.

#define V0_MAX 1600000

__device__ int g_inv[V0_MAX];

// K1: fill inverse map with -1 (vectorized, 6.4MB)
__global__ void fill_inv_kernel(int n) {
    int t = blockIdx.x * blockDim.x + threadIdx.x;
    int4* p = (int4*)g_inv;
    int n4 = n >> 2;
    if (t < n4) {
        p[t] = make_int4(-1, -1, -1, -1);
    }
}

// K2: composed index chase, write source row id
__global__ void build_inv_kernel(const int* __restrict__ idx0,
                                 const int* __restrict__ idx1,
                                 const int* __restrict__ idx2,
                                 int n_rows) {
    int i = blockIdx.x * blockDim.x + threadIdx.x;
    if (i >= n_rows) return;
    int j = __ldg(&idx2[i]);
    int k = __ldg(&idx1[j]);
    int m = __ldg(&idx0[k]);
    g_inv[m] = i;
}

// K3: single full-bandwidth output pass.
// 16 threads per row (16 x float4 = 64 floats). inv[row] broadcast within the
// half-warp; 98.5% of rows stream zeros, 1.5% gather their x row.
__global__ void emit_kernel(const float4* __restrict__ x,
                            float4* __restrict__ out,
                            long long n4) {
    long long t = (long long)blockIdx.x * blockDim.x + threadIdx.x;
    if (t >= n4) return;
    long long row = t >> 4;
    int lane = (int)(t & 15);
    int v = __ldg(&g_inv[row]);
    float4 val;
    if (v >= 0) {
        val = __ldg(&x[(long long)v * 16 + lane]);
    } else {
        val = make_float4(0.f, 0.f, 0.f, 0.f);
    }
    out[t] = val;
}

extern "C" void kernel_launch(void* const* d_in, const int* in_sizes, int n_in,
                              void* d_out, int out_size) {
    const float* x   = (const float*)d_in[0];
    const int* idx0  = (const int*)d_in[1];
    const int* idx1  = (const int*)d_in[2];
    const int* idx2  = (const int*)d_in[3];
    float* out       = (float*)d_out;

    const int F = 64;
    int n_rows = in_sizes[0] / F;            // 25000
    int v0 = out_size / F;                   // 1600000
    long long n4 = (long long)out_size / 4;  // float4 count of output (25.6M)

    // K1: inv = -1
    {
        int n4i = v0 / 4;                    // 400000 int4
        int threads = 256;
        int blocks = (n4i + threads - 1) / threads;
        fill_inv_kernel<<<blocks, threads>>>(v0);
    }

    // K2: inv[composed(i)] = i
    {
        int threads = 256;
        int blocks = (n_rows + threads - 1) / threads;
        build_inv_kernel<<<blocks, threads>>>(idx0, idx1, idx2, n_rows);
    }

    // K3: single output pass at write roofline
    {
        int threads = 256;
        long long blocks = (n4 + threads - 1) / threads; // 100000
        emit_kernel<<<(int)blocks, threads>>>((const float4*)x, (float4*)out, n4);
    }
}